// round 14
// baseline (speedup 1.0000x reference)
#include <cuda_runtime.h>
#include <cuda_bf16.h>
#include <math.h>

#define BB 32
#define CC 64
#define LL 512
#define VV 8192
#define NTOK_MAX (BB*LL)      /* 16384 */
#define NELEM (BB*CC*LL)      /* 1048576 */
#define TOKB 256              /* tokens per block, TPT1 kernel */
#define TR 128                /* codebook rows staged per tile */
#define MMA_W 0.009f          /* bf16 dot-error window (bound 3.9e-3 x2 + margin) */

// packed f32x2 helpers (sm_100+): lanewise IEEE fma on two packed floats
#define FMA_F32X2(d, a, b, c) \
    asm("fma.rn.f32x2 %0, %1, %2, %3;" : "=l"(d) : "l"(a), "l"(b), "l"(c))
#define UNPACK_F32X2(lo, hi, in) \
    asm("mov.b64 {%0, %1}, %2;" : "=r"(lo), "=r"(hi) : "l"(in))

// ---------------- device scratch (no malloc allowed) ----------------
__device__ float g_cbn[VV*CC];            // normalized codebook fp32, 2MB
__device__ unsigned g_cbb[VV*32];         // normalized codebook bf16x2, 1MB
__device__ unsigned g_cbp[VV*32];         // MMA-fragment-permuted bf16 codebook, 1MB
__device__ float g_frest[NELEM];          // residual, 4MB
__device__ float g_fhat[NELEM];           // reconstruction, 4MB
__device__ float g_rest_tok[NTOK_MAX*CC]; // downsampled+normalized tokens
__device__ int   g_idx[NTOK_MAX];         // selected codes
__device__ float g_pval[NTOK_MAX*64];     // per-vocab-split partial best val
__device__ int   g_pidx[NTOK_MAX*64];     // per-vocab-split partial best idx
__device__ int   g_cand_idx[NTOK_MAX*32]; // MMA candidates: [tok][split<4][8]
__device__ int   g_cand_cnt[NTOK_MAX*4];  // counts per (tok, split); 255=overflow
__device__ float g_loss;                  // sum of squared err accum

// ---------------- codebook row-normalize + bf16 mirror ----------------
__global__ void normalize_cb_kernel(const float* __restrict__ ew) {
    int row = blockIdx.x;
    int lane = threadIdx.x;                 // 32 threads, 2 floats each
    float2 v = reinterpret_cast<const float2*>(ew + row*CC)[lane];
    float ss = v.x*v.x + v.y*v.y;
    #pragma unroll
    for (int off = 16; off > 0; off >>= 1)
        ss += __shfl_xor_sync(0xffffffffu, ss, off);
    float den = fmaxf(__fsqrt_rn(ss), 1e-12f);
    float2 o;
    o.x = __fdiv_rn(v.x, den);
    o.y = __fdiv_rn(v.y, den);
    reinterpret_cast<float2*>(g_cbn + row*CC)[lane] = o;
    __nv_bfloat162 h = __float22bfloat162_rn(make_float2(o.x, o.y));
    g_cbb[row*32 + lane] = *reinterpret_cast<unsigned*>(&h);
}

// ---------------- permute codebook into m16n8k16 B-fragment layout --------
// dest uint D = group*256 + kk*64 + lane*2 + slot, lane = g*4 + t
// src  = cbb[(group*8 + g)*32 + (t + 4*slot + 8*kk)]
__global__ void permute_cb_kernel() {
    int D = blockIdx.x*256 + threadIdx.x;       // 0 .. VV*32-1
    int group = D >> 8;
    int rem   = D & 255;
    int kk    = rem >> 6;
    int lane  = (rem >> 1) & 31;
    int slot  = rem & 1;
    int g = lane >> 2, t = lane & 3;
    g_cbp[D] = g_cbb[(group*8 + g)*32 + (t + 4*slot + 8*kk)];
}

// ---------------- init residual / fhat / loss ----------------
__global__ void init_kernel(const float* __restrict__ f) {
    int i = blockIdx.x*256 + threadIdx.x;
    if (i < NELEM) { g_frest[i] = f[i]; g_fhat[i] = 0.f; }
    if (i == 0) g_loss = 0.f;
}

// ---------- fused area-downsample + row-normalize: warp per token ----------
__global__ void ds_norm_kernel(int s, int r, int ntok) {
    int t = blockIdx.x*8 + (threadIdx.x >> 5);
    if (t >= ntok) return;
    int lane = threadIdx.x & 31;
    int b = t / s, p = t - b*s;
    const float* s0 = g_frest + (b*CC + 2*lane)*LL + p*r;
    const float* s1 = s0 + LL;
    float va = 0.f, vb = 0.f;
    for (int j = 0; j < r; ++j) va += s0[j];
    for (int j = 0; j < r; ++j) vb += s1[j];
    float inv = 1.0f / (float)r;            // r power of two -> exact
    va *= inv; vb *= inv;
    float ss = va*va + vb*vb;
    #pragma unroll
    for (int off = 16; off > 0; off >>= 1)
        ss += __shfl_xor_sync(0xffffffffu, ss, off);
    float den = fmaxf(__fsqrt_rn(ss), 1e-12f);
    float2 o;
    o.x = __fdiv_rn(va, den);
    o.y = __fdiv_rn(vb, den);
    reinterpret_cast<float2*>(g_rest_tok)[t*32 + lane] = o;
}

// ------------- cosine argmax TPT1 (ntok<512): validated fp32 kernel --------
__global__ void __launch_bounds__(256) argmax_kernel(int ntok, int chunk, int vs) {
    __shared__ __align__(16) float4 s_cb[TR*16];   // 32KB tile

    int tid = threadIdx.x;
    int tg  = blockIdx.x * TOKB + tid;
    int tcl = (tg < ntok) ? tg : (ntok - 1);

    unsigned long long tok[32];
    {
        const ulonglong2* p =
            reinterpret_cast<const ulonglong2*>(g_rest_tok + tcl*CC);
        #pragma unroll
        for (int j = 0; j < 16; ++j) {
            ulonglong2 u = p[j];
            tok[2*j]   = u.x;
            tok[2*j+1] = u.y;
        }
    }

    float best = -1e30f; int bidx = 0;
    int vstart = blockIdx.y * chunk;
    int ntiles = chunk / TR;

    for (int tile = 0; tile < ntiles; ++tile) {
        __syncthreads();
        const float4* src = reinterpret_cast<const float4*>(g_cbn)
                          + (size_t)(vstart + tile*TR) * 16;
        #pragma unroll
        for (int k = 0; k < (TR*16)/256; ++k)
            s_cb[tid + k*256] = src[tid + k*256];
        __syncthreads();

        const ulonglong2* cb = reinterpret_cast<const ulonglong2*>(s_cb);
        int vbase = vstart + tile*TR;

        ulonglong2 cur[16], nxt[16];
        #pragma unroll
        for (int j = 0; j < 16; ++j) cur[j] = cb[j];

        #pragma unroll 1
        for (int row = 0; row < TR; row += 2) {
            #pragma unroll
            for (int j = 0; j < 16; ++j) nxt[j] = cb[(row+1)*16 + j];
            {
                unsigned long long a01 = 0ull, a23 = 0ull;
                #pragma unroll
                for (int j = 0; j < 16; ++j) {
                    FMA_F32X2(a01, cur[j].x, tok[2*j],   a01);
                    FMA_F32X2(a23, cur[j].y, tok[2*j+1], a23);
                }
                unsigned uax, uay, uaz, uaw;
                UNPACK_F32X2(uax, uay, a01);
                UNPACK_F32X2(uaz, uaw, a23);
                float d = (__uint_as_float(uax) + __uint_as_float(uay))
                        + (__uint_as_float(uaz) + __uint_as_float(uaw));
                if (d > best) { best = d; bidx = vbase + row; }
            }
            if (row + 2 < TR) {
                #pragma unroll
                for (int j = 0; j < 16; ++j) cur[j] = cb[(row+2)*16 + j];
            }
            {
                unsigned long long a01 = 0ull, a23 = 0ull;
                #pragma unroll
                for (int j = 0; j < 16; ++j) {
                    FMA_F32X2(a01, nxt[j].x, tok[2*j],   a01);
                    FMA_F32X2(a23, nxt[j].y, tok[2*j+1], a23);
                }
                unsigned uax, uay, uaz, uaw;
                UNPACK_F32X2(uax, uay, a01);
                UNPACK_F32X2(uaz, uaw, a23);
                float d = (__uint_as_float(uax) + __uint_as_float(uay))
                        + (__uint_as_float(uaz) + __uint_as_float(uaw));
                if (d > best) { best = d; bidx = vbase + row + 1; }
            }
        }
    }

    if (tg < ntok) {
        if (vs == 1) g_idx[tg] = bidx;
        else { g_pval[tg*64 + blockIdx.y] = best; g_pidx[tg*64 + blockIdx.y] = bidx; }
    }
}

// ------------- cosine argmax TPT2 (512<=ntok<4096): validated -------------
__global__ void __launch_bounds__(256) argmax2_kernel(int ntok, int chunk, int vs) {
    __shared__ __align__(16) float4 s_cb[TR*16];   // 32KB tile

    int tid = threadIdx.x;
    int tgA = blockIdx.x * 512 + tid;
    int tgB = tgA + 256;
    int cA = (tgA < ntok) ? tgA : (ntok - 1);
    int cB = (tgB < ntok) ? tgB : (ntok - 1);

    unsigned long long ta[32], tb[32];
    {
        const ulonglong2* p =
            reinterpret_cast<const ulonglong2*>(g_rest_tok + cA*CC);
        const ulonglong2* q =
            reinterpret_cast<const ulonglong2*>(g_rest_tok + cB*CC);
        #pragma unroll
        for (int j = 0; j < 16; ++j) {
            ulonglong2 u = p[j]; ta[2*j] = u.x; ta[2*j+1] = u.y;
            ulonglong2 w = q[j]; tb[2*j] = w.x; tb[2*j+1] = w.y;
        }
    }

    float bestA = -1e30f, bestB = -1e30f; int idxA = 0, idxB = 0;
    int vstart = blockIdx.y * chunk;
    int ntiles = chunk / TR;

    for (int tile = 0; tile < ntiles; ++tile) {
        __syncthreads();
        const float4* src = reinterpret_cast<const float4*>(g_cbn)
                          + (size_t)(vstart + tile*TR) * 16;
        #pragma unroll
        for (int k = 0; k < (TR*16)/256; ++k)
            s_cb[tid + k*256] = src[tid + k*256];
        __syncthreads();

        const ulonglong2* cb = reinterpret_cast<const ulonglong2*>(s_cb);
        int vbase = vstart + tile*TR;

        ulonglong2 bufA[8], bufB[8];
        #pragma unroll
        for (int j = 0; j < 8; ++j) bufA[j] = cb[j];

        #pragma unroll 1
        for (int row = 0; row < TR; ++row) {
            unsigned long long a01A = 0ull, a23A = 0ull;
            unsigned long long a01B = 0ull, a23B = 0ull;

            #pragma unroll
            for (int j = 0; j < 8; ++j) bufB[j] = cb[row*16 + 8 + j];
            #pragma unroll
            for (int j = 0; j < 8; ++j) {
                FMA_F32X2(a01A, bufA[j].x, ta[2*j],   a01A);
                FMA_F32X2(a23A, bufA[j].y, ta[2*j+1], a23A);
                FMA_F32X2(a01B, bufA[j].x, tb[2*j],   a01B);
                FMA_F32X2(a23B, bufA[j].y, tb[2*j+1], a23B);
            }
            if (row + 1 < TR) {
                #pragma unroll
                for (int j = 0; j < 8; ++j) bufA[j] = cb[(row+1)*16 + j];
            }
            #pragma unroll
            for (int j = 8; j < 16; ++j) {
                FMA_F32X2(a01A, bufB[j-8].x, ta[2*j],   a01A);
                FMA_F32X2(a23A, bufB[j-8].y, ta[2*j+1], a23A);
                FMA_F32X2(a01B, bufB[j-8].x, tb[2*j],   a01B);
                FMA_F32X2(a23B, bufB[j-8].y, tb[2*j+1], a23B);
            }

            unsigned x0, x1, x2, x3;
            UNPACK_F32X2(x0, x1, a01A);
            UNPACK_F32X2(x2, x3, a23A);
            float dA = (__uint_as_float(x0) + __uint_as_float(x1))
                     + (__uint_as_float(x2) + __uint_as_float(x3));
            if (dA > bestA) { bestA = dA; idxA = vbase + row; }
            UNPACK_F32X2(x0, x1, a01B);
            UNPACK_F32X2(x2, x3, a23B);
            float dB = (__uint_as_float(x0) + __uint_as_float(x1))
                     + (__uint_as_float(x2) + __uint_as_float(x3));
            if (dB > bestB) { bestB = dB; idxB = vbase + row; }
        }
    }

    if (tgA < ntok) {
        if (vs == 1) g_idx[tgA] = idxA;
        else { g_pval[tgA*64 + blockIdx.y] = bestA; g_pidx[tgA*64 + blockIdx.y] = idxA; }
    }
    if (tgB < ntok) {
        if (vs == 1) g_idx[tgB] = idxB;
        else { g_pval[tgB*64 + blockIdx.y] = bestB; g_pidx[tgB*64 + blockIdx.y] = idxB; }
    }
}

// -------- per-thread windowed candidate state for the MMA path --------
struct CandState {
    float bmax;
    float cv[4];
    int   ci[4];
    int   n;
    int   ovf;
};
__device__ __forceinline__ void cand_init(CandState& st) {
    st.bmax = -1e30f; st.n = 0; st.ovf = 0;
}
__device__ __forceinline__ void cand_upd(CandState& st, float v, int idx) {
    if (v >= st.bmax - MMA_W) {
        if (v > st.bmax) st.bmax = v;
        if (st.n < 4) { st.cv[st.n] = v; st.ci[st.n] = idx; st.n++; }
        else {
            int k = 0;
            #pragma unroll
            for (int i = 0; i < 4; ++i)
                if (st.cv[i] >= st.bmax - MMA_W) {
                    st.cv[k] = st.cv[i]; st.ci[k] = st.ci[i]; ++k;
                }
            if (k < 4) { st.cv[k] = v; st.ci[k] = idx; st.n = k + 1; }
            else st.ovf = 1;
        }
    }
}

// ------------- cosine argmax MMA (ntok>=4096): mma.sync bf16 --------------
// 256 thr = 8 warps; warp owns 16 tokens; block = 128 tokens. Per 128-code
// tile (16 KB straight copy of pre-permuted g_cbp): 16 n-tiles x 4 chained
// m16n8k16 bf16 MMAs. A fragments in regs (loaded once). Candidates within
// MMA_W of running max kept (cap 4/thread-row, overflow -> exact full scan).
__global__ void __launch_bounds__(256) argmax_mma_kernel(int ntok, int ns) {
    __shared__ __align__(16) unsigned sB[TR*32];   // 16KB permuted tile

    int tid  = threadIdx.x;
    int w    = tid >> 5;
    int lane = tid & 31;
    int g = lane >> 2, t = lane & 3;

    int tok0 = blockIdx.x*128 + w*16;
    int rowA = tok0 + g;        // token for D rows 0-7
    int rowB = tok0 + g + 8;    // token for D rows 8-15

    // A fragments: a[kk][0..3], one-time load+convert from fp32 tokens
    unsigned afr[4][4];
    {
        const float2* pA = reinterpret_cast<const float2*>(g_rest_tok + rowA*CC);
        const float2* pB = reinterpret_cast<const float2*>(g_rest_tok + rowB*CC);
        #pragma unroll
        for (int kk = 0; kk < 4; ++kk) {
            float2 v;
            __nv_bfloat162 h;
            v = pA[t + 8*kk];     h = __float22bfloat162_rn(v);
            afr[kk][0] = *reinterpret_cast<unsigned*>(&h);
            v = pB[t + 8*kk];     h = __float22bfloat162_rn(v);
            afr[kk][1] = *reinterpret_cast<unsigned*>(&h);
            v = pA[t + 4 + 8*kk]; h = __float22bfloat162_rn(v);
            afr[kk][2] = *reinterpret_cast<unsigned*>(&h);
            v = pB[t + 4 + 8*kk]; h = __float22bfloat162_rn(v);
            afr[kk][3] = *reinterpret_cast<unsigned*>(&h);
        }
    }

    CandState stA, stB;
    cand_init(stA); cand_init(stB);

    int codes_split = VV / ns;
    int tb0 = blockIdx.y * codes_split;
    int tiles = codes_split / TR;

    for (int tile = 0; tile < tiles; ++tile) {
        __syncthreads();
        {   // straight 16KB coalesced copy (pre-permuted layout)
            const uint4* src = reinterpret_cast<const uint4*>(
                g_cbp + (size_t)(tb0 + tile*TR) * 32);
            uint4* dst = reinterpret_cast<uint4*>(sB);
            #pragma unroll
            for (int k = 0; k < 4; ++k)
                dst[tid + k*256] = src[tid + k*256];
        }
        __syncthreads();

        const uint2* sB2 = reinterpret_cast<const uint2*>(sB);
        int cbase = tb0 + tile*TR;

        #pragma unroll 2
        for (int nt = 0; nt < 16; ++nt) {
            float d0 = 0.f, d1 = 0.f, d2 = 0.f, d3 = 0.f;
            #pragma unroll
            for (int kk = 0; kk < 4; ++kk) {
                uint2 b = sB2[(nt*4 + kk)*32 + lane];
                asm volatile(
                    "mma.sync.aligned.m16n8k16.row.col.f32.bf16.bf16.f32 "
                    "{%0,%1,%2,%3}, {%4,%5,%6,%7}, {%8,%9}, {%0,%1,%2,%3};\n"
                    : "+f"(d0), "+f"(d1), "+f"(d2), "+f"(d3)
                    : "r"(afr[kk][0]), "r"(afr[kk][1]),
                      "r"(afr[kk][2]), "r"(afr[kk][3]),
                      "r"(b.x), "r"(b.y));
            }
            int c0 = cbase + nt*8 + 2*t;
            cand_upd(stA, d0, c0);
            cand_upd(stA, d1, c0 + 1);
            cand_upd(stB, d2, c0);
            cand_upd(stB, d3, c0 + 1);
        }
    }

    // quad reduce (lanes differing in bits 0,1) + candidate write, per row
    #pragma unroll
    for (int r2 = 0; r2 < 2; ++r2) {
        CandState& st = r2 ? stB : stA;
        int tok = r2 ? rowB : rowA;
        float gb = st.bmax;
        gb = fmaxf(gb, __shfl_xor_sync(0xffffffffu, gb, 1));
        gb = fmaxf(gb, __shfl_xor_sync(0xffffffffu, gb, 2));
        int ov = st.ovf;
        ov |= __shfl_xor_sync(0xffffffffu, ov, 1);
        ov |= __shfl_xor_sync(0xffffffffu, ov, 2);

        // filter my candidates vs global (quad) max
        int c = 0;
        int keep[4];
        for (int i = 0; i < st.n; ++i)
            if (st.cv[i] >= gb - MMA_W) keep[c++] = st.ci[i];

        // prefix across the 4 quad lanes
        int base = lane & ~3;
        int total = 0, start = 0;
        #pragma unroll
        for (int i = 0; i < 4; ++i) {
            int ci = __shfl_sync(0xffffffffu, c, base + i);
            if (i < t) start += ci;
            total += ci;
        }
        int sp = blockIdx.y;
        if (ov || total > 8) {
            if (t == 0) g_cand_cnt[tok*4 + sp] = 255;
        } else {
            if (t == 0) g_cand_cnt[tok*4 + sp] = total;
            for (int i = 0; i < c; ++i)
                g_cand_idx[tok*32 + sp*8 + start + i] = keep[i];
        }
    }
}

// ------------- exact fp32 dot (bit-identical validated chain) -------------
__device__ __forceinline__ float exact_dot(int v, const unsigned long long* tok) {
    const ulonglong2* row = reinterpret_cast<const ulonglong2*>(g_cbn + v*CC);
    unsigned long long a01 = 0ull, a23 = 0ull;
    #pragma unroll
    for (int j = 0; j < 16; ++j) {
        ulonglong2 u = row[j];
        FMA_F32X2(a01, u.x, tok[2*j],   a01);
        FMA_F32X2(a23, u.y, tok[2*j+1], a23);
    }
    unsigned x0, x1, x2, x3;
    UNPACK_F32X2(x0, x1, a01);
    UNPACK_F32X2(x2, x3, a23);
    return (__uint_as_float(x0) + __uint_as_float(x1))
         + (__uint_as_float(x2) + __uint_as_float(x3));
}

// ------------- rescore candidates exactly -> g_idx ------------------------
__global__ void rescore_kernel(int ntok, int ns) {
    int t = blockIdx.x*128 + threadIdx.x;
    if (t >= ntok) return;
    unsigned long long tok[32];
    const ulonglong2* p = reinterpret_cast<const ulonglong2*>(g_rest_tok + t*CC);
    #pragma unroll
    for (int j = 0; j < 16; ++j) {
        ulonglong2 u = p[j];
        tok[2*j] = u.x; tok[2*j+1] = u.y;
    }
    bool full = false;
    float best = -1e30f; int bi = 0;
    for (int sp = 0; sp < ns && !full; ++sp) {
        int cnt = g_cand_cnt[t*4 + sp];
        if (cnt == 255) { full = true; break; }
        for (int i = 0; i < cnt; ++i) {
            int v = g_cand_idx[t*32 + sp*8 + i];
            float d = exact_dot(v, tok);
            if (d > best || (d == best && v < bi)) { best = d; bi = v; }
        }
    }
    if (full) {
        best = -1e30f; bi = 0;
        for (int v = 0; v < VV; ++v) {
            float d = exact_dot(v, tok);
            if (d > best) { best = d; bi = v; }
        }
    }
    g_idx[t] = bi;
}

// ---------------- reduce vocab splits per token (vs>1 only) ----------------
__global__ void reduce_kernel(int ntok, int vs) {
    int t = blockIdx.x*256 + threadIdx.x;
    if (t >= ntok) return;
    float bv = g_pval[t*64]; int bi = g_pidx[t*64];
    for (int sp = 1; sp < vs; ++sp) {
        float ov = g_pval[t*64 + sp]; int oi = g_pidx[t*64 + sp];
        if (ov > bv || (ov == bv && oi < bi)) { bv = ov; bi = oi; }
    }
    g_idx[t] = bi;
}

// ---------------- fused gather + upsample + Phi conv + residual update + loss ----------------
#define TL 64
#define PHI_SMEM_FLOATS (CC*(TL+2) + CC*193 + CC)
__global__ void __launch_bounds__(256) phi_update_kernel(
    const float* __restrict__ f, const float* __restrict__ ew,
    const float* __restrict__ phiw, const float* __restrict__ phib,
    int s, int pidx, float* __restrict__ outp)
{
    extern __shared__ float sm[];
    float* tile = sm;                 // [64][66]
    float* ws   = sm + CC*(TL+2);     // [64][193]
    float* bs   = ws + CC*193;        // [64]

    int b  = blockIdx.x >> 3;
    int l0 = (blockIdx.x & 7) * TL;
    int tid = threadIdx.x;

    const float* wsrc = phiw + pidx*CC*CC*3;
    for (int i = tid; i < CC*192; i += 256) {
        int co = i / 192, rem = i - co*192;
        ws[co*193 + rem] = wsrc[i];
    }
    if (tid < CC) bs[tid] = phib[pidx*CC + tid];

    for (int i = tid; i < CC*(TL+2); i += 256) {
        int ci = i / (TL+2), j = i - ci*(TL+2);
        int l = l0 + j - 1;
        float v = 0.f;
        if (l >= 0 && l < LL) {
            int tokp = (l * s) >> 9;
            int code = g_idx[b*s + tokp];
            v = ew[code*CC + ci];
        }
        tile[ci*(TL+2) + j] = v;
    }
    __syncthreads();

    int co = tid & 63;
    int pbase = (tid >> 6) * 16;
    float acc[16];
    #pragma unroll
    for (int p = 0; p < 16; ++p) acc[p] = 0.f;

    for (int ci = 0; ci < CC; ++ci) {
        const float* wr = ws + co*193 + ci*3;
        float w0 = wr[0], w1 = wr[1], w2 = wr[2];
        const float* hr = tile + ci*(TL+2) + pbase;
        float h[18];
        #pragma unroll
        for (int j = 0; j < 18; ++j) h[j] = hr[j];
        #pragma unroll
        for (int p = 0; p < 16; ++p)
            acc[p] = fmaf(w0, h[p], fmaf(w1, h[p+1], fmaf(w2, h[p+2], acc[p])));
    }

    float ss = 0.f;
    float bb = bs[co];
    #pragma unroll
    for (int p = 0; p < 16; ++p) {
        int l = l0 + pbase + p;
        float hc = tile[co*(TL+2) + pbase + p + 1];
        float y = 0.5f*hc + 0.5f*(acc[p] + bb);
        int gi = (b*CC + co)*LL + l;
        float fh = g_fhat[gi] + y;
        if (outp) {
            outp[gi] = fh;                 // last scale: write output directly
        } else {
            g_fhat[gi] = fh;
            g_frest[gi] -= y;
        }
        float d = fh - f[gi];
        ss = fmaf(d, d, ss);
    }

    #pragma unroll
    for (int off = 16; off > 0; off >>= 1)
        ss += __shfl_xor_sync(0xffffffffu, ss, off);
    __shared__ float red[8];
    int lane = tid & 31, warp = tid >> 5;
    if (lane == 0) red[warp] = ss;
    __syncthreads();
    if (tid == 0) {
        float tot = 0.f;
        #pragma unroll
        for (int w = 0; w < 8; ++w) tot += red[w];
        atomicAdd(&g_loss, tot);
    }
}

// ---------------- tail: loss scalar (+ zero any padding) ----------------
__global__ void loss_kernel(float* __restrict__ out, int out_size) {
    int i = NELEM + blockIdx.x*256 + threadIdx.x;
    if (i >= out_size) return;
    out[i] = (i == NELEM) ? g_loss * (1.25f / (10.0f * (float)NELEM)) : 0.f;
}

// ---------------- launch ----------------
extern "C" void kernel_launch(void* const* d_in, const int* in_sizes, int n_in,
                              void* d_out, int out_size) {
    // Bind inputs BY ELEMENT COUNT (pairwise distinct -> ordering-immune)
    const float* f    = nullptr;
    const float* ew   = nullptr;
    const float* phiw = nullptr;
    const float* phib = nullptr;
    for (int i = 0; i < n_in; ++i) {
        switch (in_sizes[i]) {
            case 1048576: f    = (const float*)d_in[i]; break;
            case 524288:  ew   = (const float*)d_in[i]; break;
            case 49152:   phiw = (const float*)d_in[i]; break;
            case 256:     phib = (const float*)d_in[i]; break;
            default: break;
        }
    }
    float* out = (float*)d_out;

    const int seg[10] = {1,2,4,8,16,32,64,128,256,512};

    // pmap: bit-exact float64 replication of np.linspace + np.argmin(first-wins)
    int pmap[10];
    {
        double start = 1.0 / 12.0;
        double stop  = 1.0 - 1.0 / 12.0;
        double delta = stop - start;
        double step  = delta / 3.0;
        double ticks[4];
        for (int i = 0; i < 4; ++i) ticks[i] = (double)i * step + start;
        ticks[3] = stop;
        for (int si = 0; si < 10; ++si) {
            double x = (double)si / 9.0;
            int best = 0;
            double bd = fabs(ticks[0] - x);
            for (int i = 1; i < 4; ++i) {
                double d = fabs(ticks[i] - x);
                if (d < bd) { bd = d; best = i; }
            }
            pmap[si] = best;
        }
    }

    cudaFuncSetAttribute(phi_update_kernel,
                         cudaFuncAttributeMaxDynamicSharedMemorySize,
                         PHI_SMEM_FLOATS * (int)sizeof(float));

    normalize_cb_kernel<<<VV, 32>>>(ew);
    permute_cb_kernel<<<VV*32/256, 256>>>();
    init_kernel<<<(NELEM + 255)/256, 256>>>(f);

    for (int si = 0; si < 10; ++si) {
        int s = seg[si];
        int ntok = BB * s;
        int r = LL / s;

        ds_norm_kernel<<<(ntok + 7)/8, 256>>>(s, r, ntok);

        if (ntok >= 4096) {
            int ns = 16384 / ntok;             // 4 / 2 / 1 -> 128 blocks
            dim3 agrid(ntok/128, ns);
            argmax_mma_kernel<<<agrid, 256>>>(ntok, ns);
            rescore_kernel<<<(ntok + 127)/128, 128>>>(ntok, ns);
        } else if (ntok >= 512) {
            int xblocks = ntok / 512;
            int vs = 1;
            while (xblocks * vs < 296 && vs < 64) vs <<= 1;
            int chunk = VV / vs;
            dim3 agrid(xblocks, vs);
            argmax2_kernel<<<agrid, 256>>>(ntok, chunk, vs);
            if (vs > 1) reduce_kernel<<<(ntok + 255)/256, 256>>>(ntok, vs);
        } else {
            int xblocks = (ntok + TOKB - 1)/TOKB;
            int vs = 1;
            while (xblocks * vs < 296 && vs < 64) vs <<= 1;
            int chunk = VV / vs;
            dim3 agrid(xblocks, vs);
            argmax_kernel<<<agrid, 256>>>(ntok, chunk, vs);
            if (vs > 1) reduce_kernel<<<(ntok + 255)/256, 256>>>(ntok, vs);
        }

        phi_update_kernel<<<BB*8, 256, PHI_SMEM_FLOATS*(int)sizeof(float)>>>(
            f, ew, phiw, phib, s, pmap[si], (si == 9) ? out : nullptr);
    }

    loss_kernel<<<(out_size - NELEM + 255)/256, 256>>>(out, out_size);
}

// round 15
// speedup vs baseline: 43.3821x; 43.3821x over previous
#include <cuda_runtime.h>
#include <math.h>

#define BB 32
#define CC 64
#define LL 512
#define VV 8192
#define NTOK_MAX (BB*LL)      /* 16384 */
#define NELEM (BB*CC*LL)      /* 1048576 */
#define TOKB 256              /* tokens per block, TPT1 kernel */
#define TR 128                /* codebook rows staged per tile */

// packed f32x2 helpers (sm_100+): lanewise IEEE fma on two packed floats
#define FMA_F32X2(d, a, b, c) \
    asm("fma.rn.f32x2 %0, %1, %2, %3;" : "=l"(d) : "l"(a), "l"(b), "l"(c))
#define UNPACK_F32X2(lo, hi, in) \
    asm("mov.b64 {%0, %1}, %2;" : "=r"(lo), "=r"(hi) : "l"(in))

// ---------------- device scratch (no malloc allowed) ----------------
__device__ float g_cbn[VV*CC];            // normalized codebook, 2MB
__device__ float g_frest[NELEM];          // residual, 4MB
__device__ float g_fhat[NELEM];           // reconstruction, 4MB
__device__ float g_rest_tok[NTOK_MAX*CC]; // downsampled+normalized tokens
__device__ int   g_idx[NTOK_MAX];         // selected codes
__device__ float g_pval[NTOK_MAX*64];     // per-vocab-split partial best val
__device__ int   g_pidx[NTOK_MAX*64];     // per-vocab-split partial best idx
__device__ float g_loss;                  // sum of squared err accum

// ---------------- codebook row-normalize (IEEE sqrt/div, fast-math-proof) ----
__global__ void normalize_cb_kernel(const float* __restrict__ ew) {
    int row = blockIdx.x;
    int lane = threadIdx.x;                 // 32 threads, 2 floats each
    float2 v = reinterpret_cast<const float2*>(ew + row*CC)[lane];
    float ss = v.x*v.x + v.y*v.y;
    #pragma unroll
    for (int off = 16; off > 0; off >>= 1)
        ss += __shfl_xor_sync(0xffffffffu, ss, off);
    float den = fmaxf(__fsqrt_rn(ss), 1e-12f);
    float2 o;
    o.x = __fdiv_rn(v.x, den);
    o.y = __fdiv_rn(v.y, den);
    reinterpret_cast<float2*>(g_cbn + row*CC)[lane] = o;
}

// ---------------- init residual / fhat / loss ----------------
__global__ void init_kernel(const float* __restrict__ f) {
    int i = blockIdx.x*256 + threadIdx.x;
    if (i < NELEM) { g_frest[i] = f[i]; g_fhat[i] = 0.f; }
    if (i == 0) g_loss = 0.f;
}

// ---------- fused area-downsample + row-normalize: warp per token ----------
// Accumulation order is BIT-IDENTICAL to the validated serial loop (strict
// j-order per channel); only the LOADS are batched (8 float4 in flight) to
// kill the 250-cyc-per-element serial-latency chain seen in ncu (214us @ s=1).
__global__ void ds_norm_kernel(int s, int r, int ntok) {
    int t = blockIdx.x*8 + (threadIdx.x >> 5);
    if (t >= ntok) return;
    int lane = threadIdx.x & 31;
    int b = t / s, p = t - b*s;
    const float* s0 = g_frest + (b*CC + 2*lane)*LL + p*r;
    const float* s1 = s0 + LL;
    float va = 0.f, vb = 0.f;
    if (r >= 16) {
        // p*r is a multiple of 16 floats here -> float4-aligned
        const float4* p0 = reinterpret_cast<const float4*>(s0);
        const float4* p1 = reinterpret_cast<const float4*>(s1);
        int n4 = r >> 2;
        for (int j = 0; j < n4; j += 4) {
            float4 x0 = p0[j], x1 = p0[j+1], x2 = p0[j+2], x3 = p0[j+3];
            float4 y0 = p1[j], y1 = p1[j+1], y2 = p1[j+2], y3 = p1[j+3];
            va += x0.x; vb += y0.x; va += x0.y; vb += y0.y;
            va += x0.z; vb += y0.z; va += x0.w; vb += y0.w;
            va += x1.x; vb += y1.x; va += x1.y; vb += y1.y;
            va += x1.z; vb += y1.z; va += x1.w; vb += y1.w;
            va += x2.x; vb += y2.x; va += x2.y; vb += y2.y;
            va += x2.z; vb += y2.z; va += x2.w; vb += y2.w;
            va += x3.x; vb += y3.x; va += x3.y; vb += y3.y;
            va += x3.z; vb += y3.z; va += x3.w; vb += y3.w;
        }
    } else {
        for (int j = 0; j < r; ++j) va += s0[j];
        for (int j = 0; j < r; ++j) vb += s1[j];
    }
    float inv = 1.0f / (float)r;            // r power of two -> exact
    va *= inv; vb *= inv;
    float ss = va*va + vb*vb;
    #pragma unroll
    for (int off = 16; off > 0; off >>= 1)
        ss += __shfl_xor_sync(0xffffffffu, ss, off);
    float den = fmaxf(__fsqrt_rn(ss), 1e-12f);
    float2 o;
    o.x = __fdiv_rn(va, den);
    o.y = __fdiv_rn(vb, den);
    reinterpret_cast<float2*>(g_rest_tok)[t*32 + lane] = o;
}

// ------------- cosine argmax TPT1 (ntok<512): validated fp32 kernel --------
__global__ void __launch_bounds__(256) argmax_kernel(int ntok, int chunk, int vs) {
    __shared__ __align__(16) float4 s_cb[TR*16];   // 32KB tile

    int tid = threadIdx.x;
    int tg  = blockIdx.x * TOKB + tid;
    int tcl = (tg < ntok) ? tg : (ntok - 1);

    unsigned long long tok[32];
    {
        const ulonglong2* p =
            reinterpret_cast<const ulonglong2*>(g_rest_tok + tcl*CC);
        #pragma unroll
        for (int j = 0; j < 16; ++j) {
            ulonglong2 u = p[j];
            tok[2*j]   = u.x;
            tok[2*j+1] = u.y;
        }
    }

    float best = -1e30f; int bidx = 0;
    int vstart = blockIdx.y * chunk;
    int ntiles = chunk / TR;

    for (int tile = 0; tile < ntiles; ++tile) {
        __syncthreads();
        const float4* src = reinterpret_cast<const float4*>(g_cbn)
                          + (size_t)(vstart + tile*TR) * 16;
        #pragma unroll
        for (int k = 0; k < (TR*16)/256; ++k)
            s_cb[tid + k*256] = src[tid + k*256];
        __syncthreads();

        const ulonglong2* cb = reinterpret_cast<const ulonglong2*>(s_cb);
        int vbase = vstart + tile*TR;

        ulonglong2 cur[16], nxt[16];
        #pragma unroll
        for (int j = 0; j < 16; ++j) cur[j] = cb[j];

        #pragma unroll 1
        for (int row = 0; row < TR; row += 2) {
            #pragma unroll
            for (int j = 0; j < 16; ++j) nxt[j] = cb[(row+1)*16 + j];
            {
                unsigned long long a01 = 0ull, a23 = 0ull;
                #pragma unroll
                for (int j = 0; j < 16; ++j) {
                    FMA_F32X2(a01, cur[j].x, tok[2*j],   a01);
                    FMA_F32X2(a23, cur[j].y, tok[2*j+1], a23);
                }
                unsigned uax, uay, uaz, uaw;
                UNPACK_F32X2(uax, uay, a01);
                UNPACK_F32X2(uaz, uaw, a23);
                float d = (__uint_as_float(uax) + __uint_as_float(uay))
                        + (__uint_as_float(uaz) + __uint_as_float(uaw));
                if (d > best) { best = d; bidx = vbase + row; }
            }
            if (row + 2 < TR) {
                #pragma unroll
                for (int j = 0; j < 16; ++j) cur[j] = cb[(row+2)*16 + j];
            }
            {
                unsigned long long a01 = 0ull, a23 = 0ull;
                #pragma unroll
                for (int j = 0; j < 16; ++j) {
                    FMA_F32X2(a01, nxt[j].x, tok[2*j],   a01);
                    FMA_F32X2(a23, nxt[j].y, tok[2*j+1], a23);
                }
                unsigned uax, uay, uaz, uaw;
                UNPACK_F32X2(uax, uay, a01);
                UNPACK_F32X2(uaz, uaw, a23);
                float d = (__uint_as_float(uax) + __uint_as_float(uay))
                        + (__uint_as_float(uaz) + __uint_as_float(uaw));
                if (d > best) { best = d; bidx = vbase + row + 1; }
            }
        }
    }

    if (tg < ntok) {
        if (vs == 1) g_idx[tg] = bidx;
        else { g_pval[tg*64 + blockIdx.y] = best; g_pidx[tg*64 + blockIdx.y] = bidx; }
    }
}

// ------------- cosine argmax TPT2 (ntok>=512): 2 tokens/thread, validated --
__global__ void __launch_bounds__(256) argmax2_kernel(int ntok, int chunk, int vs) {
    __shared__ __align__(16) float4 s_cb[TR*16];   // 32KB tile

    int tid = threadIdx.x;
    int tgA = blockIdx.x * 512 + tid;
    int tgB = tgA + 256;
    int cA = (tgA < ntok) ? tgA : (ntok - 1);
    int cB = (tgB < ntok) ? tgB : (ntok - 1);

    unsigned long long ta[32], tb[32];
    {
        const ulonglong2* p =
            reinterpret_cast<const ulonglong2*>(g_rest_tok + cA*CC);
        const ulonglong2* q =
            reinterpret_cast<const ulonglong2*>(g_rest_tok + cB*CC);
        #pragma unroll
        for (int j = 0; j < 16; ++j) {
            ulonglong2 u = p[j]; ta[2*j] = u.x; ta[2*j+1] = u.y;
            ulonglong2 w = q[j]; tb[2*j] = w.x; tb[2*j+1] = w.y;
        }
    }

    float bestA = -1e30f, bestB = -1e30f; int idxA = 0, idxB = 0;
    int vstart = blockIdx.y * chunk;
    int ntiles = chunk / TR;

    for (int tile = 0; tile < ntiles; ++tile) {
        __syncthreads();
        const float4* src = reinterpret_cast<const float4*>(g_cbn)
                          + (size_t)(vstart + tile*TR) * 16;
        #pragma unroll
        for (int k = 0; k < (TR*16)/256; ++k)
            s_cb[tid + k*256] = src[tid + k*256];
        __syncthreads();

        const ulonglong2* cb = reinterpret_cast<const ulonglong2*>(s_cb);
        int vbase = vstart + tile*TR;

        ulonglong2 bufA[8], bufB[8];
        #pragma unroll
        for (int j = 0; j < 8; ++j) bufA[j] = cb[j];

        #pragma unroll 1
        for (int row = 0; row < TR; ++row) {
            unsigned long long a01A = 0ull, a23A = 0ull;
            unsigned long long a01B = 0ull, a23B = 0ull;

            #pragma unroll
            for (int j = 0; j < 8; ++j) bufB[j] = cb[row*16 + 8 + j];
            #pragma unroll
            for (int j = 0; j < 8; ++j) {
                FMA_F32X2(a01A, bufA[j].x, ta[2*j],   a01A);
                FMA_F32X2(a23A, bufA[j].y, ta[2*j+1], a23A);
                FMA_F32X2(a01B, bufA[j].x, tb[2*j],   a01B);
                FMA_F32X2(a23B, bufA[j].y, tb[2*j+1], a23B);
            }
            if (row + 1 < TR) {
                #pragma unroll
                for (int j = 0; j < 8; ++j) bufA[j] = cb[(row+1)*16 + j];
            }
            #pragma unroll
            for (int j = 8; j < 16; ++j) {
                FMA_F32X2(a01A, bufB[j-8].x, ta[2*j],   a01A);
                FMA_F32X2(a23A, bufB[j-8].y, ta[2*j+1], a23A);
                FMA_F32X2(a01B, bufB[j-8].x, tb[2*j],   a01B);
                FMA_F32X2(a23B, bufB[j-8].y, tb[2*j+1], a23B);
            }

            unsigned x0, x1, x2, x3;
            UNPACK_F32X2(x0, x1, a01A);
            UNPACK_F32X2(x2, x3, a23A);
            float dA = (__uint_as_float(x0) + __uint_as_float(x1))
                     + (__uint_as_float(x2) + __uint_as_float(x3));
            if (dA > bestA) { bestA = dA; idxA = vbase + row; }
            UNPACK_F32X2(x0, x1, a01B);
            UNPACK_F32X2(x2, x3, a23B);
            float dB = (__uint_as_float(x0) + __uint_as_float(x1))
                     + (__uint_as_float(x2) + __uint_as_float(x3));
            if (dB > bestB) { bestB = dB; idxB = vbase + row; }
        }
    }

    if (tgA < ntok) {
        if (vs == 1) g_idx[tgA] = idxA;
        else { g_pval[tgA*64 + blockIdx.y] = bestA; g_pidx[tgA*64 + blockIdx.y] = idxA; }
    }
    if (tgB < ntok) {
        if (vs == 1) g_idx[tgB] = idxB;
        else { g_pval[tgB*64 + blockIdx.y] = bestB; g_pidx[tgB*64 + blockIdx.y] = idxB; }
    }
}

// ---------------- reduce vocab splits per token (vs>1 only) ----------------
__global__ void reduce_kernel(int ntok, int vs) {
    int t = blockIdx.x*256 + threadIdx.x;
    if (t >= ntok) return;
    float bv = g_pval[t*64]; int bi = g_pidx[t*64];
    for (int sp = 1; sp < vs; ++sp) {
        float ov = g_pval[t*64 + sp]; int oi = g_pidx[t*64 + sp];
        if (ov > bv || (ov == bv && oi < bi)) { bv = ov; bi = oi; }
    }
    g_idx[t] = bi;
}

// ---------------- fused gather + upsample + Phi conv + residual update + loss ----------------
#define TL 64
#define PHI_SMEM_FLOATS (CC*(TL+2) + CC*193 + CC)
__global__ void __launch_bounds__(256) phi_update_kernel(
    const float* __restrict__ f, const float* __restrict__ ew,
    const float* __restrict__ phiw, const float* __restrict__ phib,
    int s, int pidx, float* __restrict__ outp)
{
    extern __shared__ float sm[];
    float* tile = sm;                 // [64][66]
    float* ws   = sm + CC*(TL+2);     // [64][193]
    float* bs   = ws + CC*193;        // [64]

    int b  = blockIdx.x >> 3;
    int l0 = (blockIdx.x & 7) * TL;
    int tid = threadIdx.x;

    const float* wsrc = phiw + pidx*CC*CC*3;
    for (int i = tid; i < CC*192; i += 256) {
        int co = i / 192, rem = i - co*192;
        ws[co*193 + rem] = wsrc[i];
    }
    if (tid < CC) bs[tid] = phib[pidx*CC + tid];

    for (int i = tid; i < CC*(TL+2); i += 256) {
        int ci = i / (TL+2), j = i - ci*(TL+2);
        int l = l0 + j - 1;
        float v = 0.f;
        if (l >= 0 && l < LL) {
            int tokp = (l * s) >> 9;
            int code = g_idx[b*s + tokp];
            v = ew[code*CC + ci];
        }
        tile[ci*(TL+2) + j] = v;
    }
    __syncthreads();

    int co = tid & 63;
    int pbase = (tid >> 6) * 16;
    float acc[16];
    #pragma unroll
    for (int p = 0; p < 16; ++p) acc[p] = 0.f;

    for (int ci = 0; ci < CC; ++ci) {
        const float* wr = ws + co*193 + ci*3;
        float w0 = wr[0], w1 = wr[1], w2 = wr[2];
        const float* hr = tile + ci*(TL+2) + pbase;
        float h[18];
        #pragma unroll
        for (int j = 0; j < 18; ++j) h[j] = hr[j];
        #pragma unroll
        for (int p = 0; p < 16; ++p)
            acc[p] = fmaf(w0, h[p], fmaf(w1, h[p+1], fmaf(w2, h[p+2], acc[p])));
    }

    float ss = 0.f;
    float bb = bs[co];
    #pragma unroll
    for (int p = 0; p < 16; ++p) {
        int l = l0 + pbase + p;
        float hc = tile[co*(TL+2) + pbase + p + 1];
        float y = 0.5f*hc + 0.5f*(acc[p] + bb);
        int gi = (b*CC + co)*LL + l;
        float fh = g_fhat[gi] + y;
        if (outp) {
            outp[gi] = fh;                 // last scale: write output directly
        } else {
            g_fhat[gi] = fh;
            g_frest[gi] -= y;
        }
        float d = fh - f[gi];
        ss = fmaf(d, d, ss);
    }

    #pragma unroll
    for (int off = 16; off > 0; off >>= 1)
        ss += __shfl_xor_sync(0xffffffffu, ss, off);
    __shared__ float red[8];
    int lane = tid & 31, warp = tid >> 5;
    if (lane == 0) red[warp] = ss;
    __syncthreads();
    if (tid == 0) {
        float tot = 0.f;
        #pragma unroll
        for (int w = 0; w < 8; ++w) tot += red[w];
        atomicAdd(&g_loss, tot);
    }
}

// ---------------- tail: loss scalar (+ zero any padding) ----------------
__global__ void loss_kernel(float* __restrict__ out, int out_size) {
    int i = NELEM + blockIdx.x*256 + threadIdx.x;
    if (i >= out_size) return;
    out[i] = (i == NELEM) ? g_loss * (1.25f / (10.0f * (float)NELEM)) : 0.f;
}

// ---------------- launch ----------------
extern "C" void kernel_launch(void* const* d_in, const int* in_sizes, int n_in,
                              void* d_out, int out_size) {
    // Bind inputs BY ELEMENT COUNT (pairwise distinct -> ordering-immune)
    const float* f    = nullptr;
    const float* ew   = nullptr;
    const float* phiw = nullptr;
    const float* phib = nullptr;
    for (int i = 0; i < n_in; ++i) {
        switch (in_sizes[i]) {
            case 1048576: f    = (const float*)d_in[i]; break;
            case 524288:  ew   = (const float*)d_in[i]; break;
            case 49152:   phiw = (const float*)d_in[i]; break;
            case 256:     phib = (const float*)d_in[i]; break;
            default: break;
        }
    }
    float* out = (float*)d_out;

    const int seg[10] = {1,2,4,8,16,32,64,128,256,512};

    // pmap: bit-exact float64 replication of np.linspace + np.argmin(first-wins)
    int pmap[10];
    {
        double start = 1.0 / 12.0;
        double stop  = 1.0 - 1.0 / 12.0;
        double delta = stop - start;
        double step  = delta / 3.0;
        double ticks[4];
        for (int i = 0; i < 4; ++i) ticks[i] = (double)i * step + start;
        ticks[3] = stop;
        for (int si = 0; si < 10; ++si) {
            double x = (double)si / 9.0;
            int best = 0;
            double bd = fabs(ticks[0] - x);
            for (int i = 1; i < 4; ++i) {
                double d = fabs(ticks[i] - x);
                if (d < bd) { bd = d; best = i; }
            }
            pmap[si] = best;
        }
    }

    cudaFuncSetAttribute(phi_update_kernel,
                         cudaFuncAttributeMaxDynamicSharedMemorySize,
                         PHI_SMEM_FLOATS * (int)sizeof(float));

    normalize_cb_kernel<<<VV, 32>>>(ew);
    init_kernel<<<(NELEM + 255)/256, 256>>>(f);

    for (int si = 0; si < 10; ++si) {
        int s = seg[si];
        int ntok = BB * s;
        int r = LL / s;

        ds_norm_kernel<<<(ntok + 7)/8, 256>>>(s, r, ntok);

        int vs;
        if (ntok >= 512) {
            int xblocks = ntok / 512;              // exact (ntok multiple of 512)
            vs = 1;
            while (xblocks * vs < 296 && vs < 64) vs <<= 1;
            int chunk = VV / vs;                   // multiple of TR=128
            dim3 agrid(xblocks, vs);
            argmax2_kernel<<<agrid, 256>>>(ntok, chunk, vs);
        } else {
            int xblocks = (ntok + TOKB - 1)/TOKB;
            vs = 1;
            while (xblocks * vs < 296 && vs < 64) vs <<= 1;
            int chunk = VV / vs;
            dim3 agrid(xblocks, vs);
            argmax_kernel<<<agrid, 256>>>(ntok, chunk, vs);
        }

        if (vs > 1)
            reduce_kernel<<<(ntok + 255)/256, 256>>>(ntok, vs);

        phi_update_kernel<<<BB*8, 256, PHI_SMEM_FLOATS*(int)sizeof(float)>>>(
            f, ew, phiw, phib, s, pmap[si], (si == 9) ? out : nullptr);
    }

    loss_kernel<<<(out_size - NELEM + 255)/256, 256>>>(out, out_size);
}

// round 16
// speedup vs baseline: 48.1830x; 1.1107x over previous
#include <cuda_runtime.h>
#include <math.h>

#define BB 32
#define CC 64
#define LL 512
#define VV 8192
#define NTOK_MAX (BB*LL)      /* 16384 */
#define NELEM (BB*CC*LL)      /* 1048576 */
#define TR 128                /* codebook rows staged per tile */

// packed f32x2 helpers (sm_100+): lanewise IEEE fma on two packed floats
#define FMA_F32X2(d, a, b, c) \
    asm("fma.rn.f32x2 %0, %1, %2, %3;" : "=l"(d) : "l"(a), "l"(b), "l"(c))
#define UNPACK_F32X2(lo, hi, in) \
    asm("mov.b64 {%0, %1}, %2;" : "=r"(lo), "=r"(hi) : "l"(in))

// ---------------- device scratch (no malloc allowed) ----------------
__device__ float g_cbn[VV*CC];            // normalized codebook, 2MB
__device__ float g_frest[NELEM];          // residual, 4MB
__device__ float g_fhat[NELEM];           // reconstruction, 4MB
__device__ float g_rest_tok[NTOK_MAX*CC]; // downsampled+normalized tokens
__device__ unsigned long long g_key[NTOK_MAX]; // packed (ordered val, VV-idx)
__device__ float g_loss;                  // sum of squared err accum

// pack (value, idx) so u64 max == (max value, lowest idx on float-equal ties)
__device__ __forceinline__ unsigned long long pack_key(float v, int idx) {
    unsigned u = __float_as_uint(v);
    u = (u & 0x80000000u) ? ~u : (u | 0x80000000u);   // monotone order-preserving
    return ((unsigned long long)u << 32) | (unsigned)(VV - idx);
}

// ---------------- codebook row-normalize (IEEE sqrt/div, fast-math-proof) ----
__global__ void normalize_cb_kernel(const float* __restrict__ ew) {
    int row = blockIdx.x;
    int lane = threadIdx.x;                 // 32 threads, 2 floats each
    float2 v = reinterpret_cast<const float2*>(ew + row*CC)[lane];
    float ss = v.x*v.x + v.y*v.y;
    #pragma unroll
    for (int off = 16; off > 0; off >>= 1)
        ss += __shfl_xor_sync(0xffffffffu, ss, off);
    float den = fmaxf(__fsqrt_rn(ss), 1e-12f);
    float2 o;
    o.x = __fdiv_rn(v.x, den);
    o.y = __fdiv_rn(v.y, den);
    reinterpret_cast<float2*>(g_cbn + row*CC)[lane] = o;
}

// ---------------- init residual / fhat / loss ----------------
__global__ void init_kernel(const float* __restrict__ f) {
    int i = blockIdx.x*256 + threadIdx.x;
    if (i < NELEM) { g_frest[i] = f[i]; g_fhat[i] = 0.f; }
    if (i == 0) g_loss = 0.f;
}

// ---------- fused area-downsample + row-normalize + key-init ----------
// Accumulation order BIT-IDENTICAL to the validated serial loop; loads batched.
__global__ void ds_norm_kernel(int s, int r, int ntok) {
    int t = blockIdx.x*8 + (threadIdx.x >> 5);
    if (t >= ntok) return;
    int lane = threadIdx.x & 31;
    int b = t / s, p = t - b*s;
    const float* s0 = g_frest + (b*CC + 2*lane)*LL + p*r;
    const float* s1 = s0 + LL;
    float va = 0.f, vb = 0.f;
    if (r >= 16) {
        const float4* p0 = reinterpret_cast<const float4*>(s0);
        const float4* p1 = reinterpret_cast<const float4*>(s1);
        int n4 = r >> 2;
        for (int j = 0; j < n4; j += 4) {
            float4 x0 = p0[j], x1 = p0[j+1], x2 = p0[j+2], x3 = p0[j+3];
            float4 y0 = p1[j], y1 = p1[j+1], y2 = p1[j+2], y3 = p1[j+3];
            va += x0.x; vb += y0.x; va += x0.y; vb += y0.y;
            va += x0.z; vb += y0.z; va += x0.w; vb += y0.w;
            va += x1.x; vb += y1.x; va += x1.y; vb += y1.y;
            va += x1.z; vb += y1.z; va += x1.w; vb += y1.w;
            va += x2.x; vb += y2.x; va += x2.y; vb += y2.y;
            va += x2.z; vb += y2.z; va += x2.w; vb += y2.w;
            va += x3.x; vb += y3.x; va += x3.y; vb += y3.y;
            va += x3.z; vb += y3.z; va += x3.w; vb += y3.w;
        }
    } else {
        for (int j = 0; j < r; ++j) va += s0[j];
        for (int j = 0; j < r; ++j) vb += s1[j];
    }
    float inv = 1.0f / (float)r;            // r power of two -> exact
    va *= inv; vb *= inv;
    float ss = va*va + vb*vb;
    #pragma unroll
    for (int off = 16; off > 0; off >>= 1)
        ss += __shfl_xor_sync(0xffffffffu, ss, off);
    float den = fmaxf(__fsqrt_rn(ss), 1e-12f);
    float2 o;
    o.x = __fdiv_rn(va, den);
    o.y = __fdiv_rn(vb, den);
    reinterpret_cast<float2*>(g_rest_tok)[t*32 + lane] = o;
    if (lane == 0) g_key[t] = 0ull;         // all valid keys are > 0
}

// ------- cosine argmax SMALL (ntok in {32,64,128,256}): subsplit layout ----
// 256 threads: token = tid & (ntok-1); sub = tid / ntok (warp-uniform ->
// broadcast LDS preserved). grid (1, 64); each block = one 128-code tile;
// each thread scans rows [sub*rps, sub*rps+rps). Same bit-exact FFMA2 chains;
// rows ascending + pack_key tie rule == lowest index.
__global__ void __launch_bounds__(256) argmax_small_kernel(int ntok) {
    __shared__ __align__(16) float4 s_cb[TR*16];   // 32KB tile
    int tid = threadIdx.x;
    int tg  = tid & (ntok - 1);
    int sub = tid / ntok;
    int subs = 256 / ntok;
    int rps = TR / subs;

    unsigned long long tok[32];
    {
        const ulonglong2* p =
            reinterpret_cast<const ulonglong2*>(g_rest_tok + tg*CC);
        #pragma unroll
        for (int j = 0; j < 16; ++j) {
            ulonglong2 u = p[j];
            tok[2*j]   = u.x;
            tok[2*j+1] = u.y;
        }
    }

    int vstart = blockIdx.y * TR;
    {
        const float4* src = reinterpret_cast<const float4*>(g_cbn)
                          + (size_t)vstart * 16;
        #pragma unroll
        for (int k = 0; k < (TR*16)/256; ++k)
            s_cb[tid + k*256] = src[tid + k*256];
    }
    __syncthreads();

    const ulonglong2* cb = reinterpret_cast<const ulonglong2*>(s_cb);
    int r0 = sub * rps;

    float best = -1e30f; int bidx = 0;
    ulonglong2 bufA[8], bufB[8];
    #pragma unroll
    for (int j = 0; j < 8; ++j) bufA[j] = cb[r0*16 + j];

    #pragma unroll 1
    for (int row = r0; row < r0 + rps; ++row) {
        unsigned long long a01 = 0ull, a23 = 0ull;
        #pragma unroll
        for (int j = 0; j < 8; ++j) bufB[j] = cb[row*16 + 8 + j];
        #pragma unroll
        for (int j = 0; j < 8; ++j) {
            FMA_F32X2(a01, bufA[j].x, tok[2*j],   a01);
            FMA_F32X2(a23, bufA[j].y, tok[2*j+1], a23);
        }
        if (row + 1 < r0 + rps) {
            #pragma unroll
            for (int j = 0; j < 8; ++j) bufA[j] = cb[(row+1)*16 + j];
        }
        #pragma unroll
        for (int j = 8; j < 16; ++j) {
            FMA_F32X2(a01, bufB[j-8].x, tok[2*j],   a01);
            FMA_F32X2(a23, bufB[j-8].y, tok[2*j+1], a23);
        }
        unsigned x0, x1, x2, x3;
        UNPACK_F32X2(x0, x1, a01);
        UNPACK_F32X2(x2, x3, a23);
        float d = (__uint_as_float(x0) + __uint_as_float(x1))
                + (__uint_as_float(x2) + __uint_as_float(x3));
        if (d > best) { best = d; bidx = vstart + row; }
    }

    atomicMax(&g_key[tg], pack_key(best, bidx));
}

// ------------- cosine argmax TPT2 (ntok>=512): validated + atomic epilogue --
__global__ void __launch_bounds__(256) argmax2_kernel(int ntok, int chunk) {
    __shared__ __align__(16) float4 s_cb[TR*16];   // 32KB tile

    int tid = threadIdx.x;
    int tgA = blockIdx.x * 512 + tid;
    int tgB = tgA + 256;
    int cA = (tgA < ntok) ? tgA : (ntok - 1);
    int cB = (tgB < ntok) ? tgB : (ntok - 1);

    unsigned long long ta[32], tb[32];
    {
        const ulonglong2* p =
            reinterpret_cast<const ulonglong2*>(g_rest_tok + cA*CC);
        const ulonglong2* q =
            reinterpret_cast<const ulonglong2*>(g_rest_tok + cB*CC);
        #pragma unroll
        for (int j = 0; j < 16; ++j) {
            ulonglong2 u = p[j]; ta[2*j] = u.x; ta[2*j+1] = u.y;
            ulonglong2 w = q[j]; tb[2*j] = w.x; tb[2*j+1] = w.y;
        }
    }

    float bestA = -1e30f, bestB = -1e30f; int idxA = 0, idxB = 0;
    int vstart = blockIdx.y * chunk;
    int ntiles = chunk / TR;

    for (int tile = 0; tile < ntiles; ++tile) {
        __syncthreads();
        const float4* src = reinterpret_cast<const float4*>(g_cbn)
                          + (size_t)(vstart + tile*TR) * 16;
        #pragma unroll
        for (int k = 0; k < (TR*16)/256; ++k)
            s_cb[tid + k*256] = src[tid + k*256];
        __syncthreads();

        const ulonglong2* cb = reinterpret_cast<const ulonglong2*>(s_cb);
        int vbase = vstart + tile*TR;

        ulonglong2 bufA[8], bufB[8];
        #pragma unroll
        for (int j = 0; j < 8; ++j) bufA[j] = cb[j];

        #pragma unroll 1
        for (int row = 0; row < TR; ++row) {
            unsigned long long a01A = 0ull, a23A = 0ull;
            unsigned long long a01B = 0ull, a23B = 0ull;

            #pragma unroll
            for (int j = 0; j < 8; ++j) bufB[j] = cb[row*16 + 8 + j];
            #pragma unroll
            for (int j = 0; j < 8; ++j) {
                FMA_F32X2(a01A, bufA[j].x, ta[2*j],   a01A);
                FMA_F32X2(a23A, bufA[j].y, ta[2*j+1], a23A);
                FMA_F32X2(a01B, bufA[j].x, tb[2*j],   a01B);
                FMA_F32X2(a23B, bufA[j].y, tb[2*j+1], a23B);
            }
            if (row + 1 < TR) {
                #pragma unroll
                for (int j = 0; j < 8; ++j) bufA[j] = cb[(row+1)*16 + j];
            }
            #pragma unroll
            for (int j = 8; j < 16; ++j) {
                FMA_F32X2(a01A, bufB[j-8].x, ta[2*j],   a01A);
                FMA_F32X2(a23A, bufB[j-8].y, ta[2*j+1], a23A);
                FMA_F32X2(a01B, bufB[j-8].x, tb[2*j],   a01B);
                FMA_F32X2(a23B, bufB[j-8].y, tb[2*j+1], a23B);
            }

            unsigned x0, x1, x2, x3;
            UNPACK_F32X2(x0, x1, a01A);
            UNPACK_F32X2(x2, x3, a23A);
            float dA = (__uint_as_float(x0) + __uint_as_float(x1))
                     + (__uint_as_float(x2) + __uint_as_float(x3));
            if (dA > bestA) { bestA = dA; idxA = vbase + row; }
            UNPACK_F32X2(x0, x1, a01B);
            UNPACK_F32X2(x2, x3, a23B);
            float dB = (__uint_as_float(x0) + __uint_as_float(x1))
                     + (__uint_as_float(x2) + __uint_as_float(x3));
            if (dB > bestB) { bestB = dB; idxB = vbase + row; }
        }
    }

    if (tgA < ntok) atomicMax(&g_key[tgA], pack_key(bestA, idxA));
    if (tgB < ntok) atomicMax(&g_key[tgB], pack_key(bestB, idxB));
}

// ---------------- fused gather + upsample + Phi conv + residual update + loss ----------------
#define TL 64
#define PHI_SMEM_FLOATS (CC*(TL+2) + CC*193 + CC)
__global__ void __launch_bounds__(256) phi_update_kernel(
    const float* __restrict__ f, const float* __restrict__ ew,
    const float* __restrict__ phiw, const float* __restrict__ phib,
    int s, int pidx, float* __restrict__ outp)
{
    extern __shared__ float sm[];
    float* tile = sm;                 // [64][66]
    float* ws   = sm + CC*(TL+2);     // [64][193]
    float* bs   = ws + CC*193;        // [64]

    int b  = blockIdx.x >> 3;
    int l0 = (blockIdx.x & 7) * TL;
    int tid = threadIdx.x;

    const float* wsrc = phiw + pidx*CC*CC*3;
    for (int i = tid; i < CC*192; i += 256) {
        int co = i / 192, rem = i - co*192;
        ws[co*193 + rem] = wsrc[i];
    }
    if (tid < CC) bs[tid] = phib[pidx*CC + tid];

    for (int i = tid; i < CC*(TL+2); i += 256) {
        int ci = i / (TL+2), j = i - ci*(TL+2);
        int l = l0 + j - 1;
        float v = 0.f;
        if (l >= 0 && l < LL) {
            int tokp = (l * s) >> 9;
            int code = VV - (int)(unsigned)(g_key[b*s + tokp] & 0xffffffffu);
            v = ew[code*CC + ci];
        }
        tile[ci*(TL+2) + j] = v;
    }
    __syncthreads();

    int co = tid & 63;
    int pbase = (tid >> 6) * 16;
    float acc[16];
    #pragma unroll
    for (int p = 0; p < 16; ++p) acc[p] = 0.f;

    for (int ci = 0; ci < CC; ++ci) {
        const float* wr = ws + co*193 + ci*3;
        float w0 = wr[0], w1 = wr[1], w2 = wr[2];
        const float* hr = tile + ci*(TL+2) + pbase;
        float h[18];
        #pragma unroll
        for (int j = 0; j < 18; ++j) h[j] = hr[j];
        #pragma unroll
        for (int p = 0; p < 16; ++p)
            acc[p] = fmaf(w0, h[p], fmaf(w1, h[p+1], fmaf(w2, h[p+2], acc[p])));
    }

    float ss = 0.f;
    float bb = bs[co];
    #pragma unroll
    for (int p = 0; p < 16; ++p) {
        int l = l0 + pbase + p;
        float hc = tile[co*(TL+2) + pbase + p + 1];
        float y = 0.5f*hc + 0.5f*(acc[p] + bb);
        int gi = (b*CC + co)*LL + l;
        float fh = g_fhat[gi] + y;
        if (outp) {
            outp[gi] = fh;                 // last scale: write output directly
        } else {
            g_fhat[gi] = fh;
            g_frest[gi] -= y;
        }
        float d = fh - f[gi];
        ss = fmaf(d, d, ss);
    }

    #pragma unroll
    for (int off = 16; off > 0; off >>= 1)
        ss += __shfl_xor_sync(0xffffffffu, ss, off);
    __shared__ float red[8];
    int lane = tid & 31, warp = tid >> 5;
    if (lane == 0) red[warp] = ss;
    __syncthreads();
    if (tid == 0) {
        float tot = 0.f;
        #pragma unroll
        for (int w = 0; w < 8; ++w) tot += red[w];
        atomicAdd(&g_loss, tot);
    }
}

// ---------------- tail: loss scalar (+ zero any padding) ----------------
__global__ void loss_kernel(float* __restrict__ out, int out_size) {
    int i = NELEM + blockIdx.x*256 + threadIdx.x;
    if (i >= out_size) return;
    out[i] = (i == NELEM) ? g_loss * (1.25f / (10.0f * (float)NELEM)) : 0.f;
}

// ---------------- launch ----------------
extern "C" void kernel_launch(void* const* d_in, const int* in_sizes, int n_in,
                              void* d_out, int out_size) {
    // Bind inputs BY ELEMENT COUNT (pairwise distinct -> ordering-immune)
    const float* f    = nullptr;
    const float* ew   = nullptr;
    const float* phiw = nullptr;
    const float* phib = nullptr;
    for (int i = 0; i < n_in; ++i) {
        switch (in_sizes[i]) {
            case 1048576: f    = (const float*)d_in[i]; break;
            case 524288:  ew   = (const float*)d_in[i]; break;
            case 49152:   phiw = (const float*)d_in[i]; break;
            case 256:     phib = (const float*)d_in[i]; break;
            default: break;
        }
    }
    float* out = (float*)d_out;

    const int seg[10] = {1,2,4,8,16,32,64,128,256,512};

    // pmap: bit-exact float64 replication of np.linspace + np.argmin(first-wins)
    int pmap[10];
    {
        double start = 1.0 / 12.0;
        double stop  = 1.0 - 1.0 / 12.0;
        double delta = stop - start;
        double step  = delta / 3.0;
        double ticks[4];
        for (int i = 0; i < 4; ++i) ticks[i] = (double)i * step + start;
        ticks[3] = stop;
        for (int si = 0; si < 10; ++si) {
            double x = (double)si / 9.0;
            int best = 0;
            double bd = fabs(ticks[0] - x);
            for (int i = 1; i < 4; ++i) {
                double d = fabs(ticks[i] - x);
                if (d < bd) { bd = d; best = i; }
            }
            pmap[si] = best;
        }
    }

    cudaFuncSetAttribute(phi_update_kernel,
                         cudaFuncAttributeMaxDynamicSharedMemorySize,
                         PHI_SMEM_FLOATS * (int)sizeof(float));

    normalize_cb_kernel<<<VV, 32>>>(ew);
    init_kernel<<<(NELEM + 255)/256, 256>>>(f);

    for (int si = 0; si < 10; ++si) {
        int s = seg[si];
        int ntok = BB * s;
        int r = LL / s;

        ds_norm_kernel<<<(ntok + 7)/8, 256>>>(s, r, ntok);

        if (ntok >= 512) {
            int xblocks = ntok / 512;              // exact (ntok multiple of 512)
            int vs = 1;
            while (xblocks * vs < 296 && vs < 64) vs <<= 1;
            int chunk = VV / vs;                   // multiple of TR=128
            dim3 agrid(xblocks, vs);
            argmax2_kernel<<<agrid, 256>>>(ntok, chunk);
        } else {
            dim3 agrid(1, VV / TR);                // 64 tile-blocks
            argmax_small_kernel<<<agrid, 256>>>(ntok);
        }

        phi_update_kernel<<<BB*8, 256, PHI_SMEM_FLOATS*(int)sizeof(float)>>>(
            f, ew, phiw, phib, s, pmap[si], (si == 9) ? out : nullptr);
    }

    loss_kernel<<<(out_size - NELEM + 255)/256, 256>>>(out, out_size);
}